// round 3
// baseline (speedup 1.0000x reference)
#include <cuda_runtime.h>

#define NSRC 20000
#define NTAR 20000
#define G    32
#define G3   (G * G * G)
#define H    0.25f
#define INVH 4.0f
#define ORIG (-4.0f)
#define FLT_BIG 3.402823466e38f
#define SBLK 128
#define NSB  ((NTAR + SBLK - 1) / SBLK)   // 157 search blocks

// Scratch — device globals (no allocation allowed). Zero-initialized at load.
__device__ int    g_cnt[G3];        // per-cell histogram (re-zeroed by scan_kernel)
__device__ int    g_off[G3 + 1];    // exclusive prefix (cell ranges)
__device__ int    g_fill[G3];       // scatter cursors (rewritten by scan each run)
__device__ int    g_scell[NSRC];    // per-source cell id
__device__ float4 g_s4[NSRC];       // cell-sorted source coords
__device__ float  g_gsum[NSB];      // per-block partial sums

__device__ __forceinline__ int cellc(float v) {
    int c = (int)floorf((v - ORIG) * INVH);
    return min(max(c, 0), G - 1);
}

// K1: histogram sources into cells, stash each source's cell id.
__global__ void count_kernel(const float* __restrict__ src) {
    int i = blockIdx.x * blockDim.x + threadIdx.x;
    if (i < NSRC) {
        float x = src[3 * i + 0];
        float y = src[3 * i + 1];
        float z = src[3 * i + 2];
        int cid = (cellc(z) * G + cellc(y)) * G + cellc(x);
        g_scell[i] = cid;
        atomicAdd(&g_cnt[cid], 1);
    }
}

// K2: single-block exclusive scan of 32768 counts (1024 threads x 32 cells).
// Writes g_off (+sentinel) and g_fill, and re-zeroes g_cnt for the next replay.
__global__ __launch_bounds__(1024) void scan_kernel() {
    __shared__ int wsum[32];
    int tid = threadIdx.x;
    int base = tid * 32;

    int v[32];
    int tot = 0;
    #pragma unroll
    for (int j = 0; j < 32; j += 4) {
        int4 q = *(const int4*)&g_cnt[base + j];
        v[j] = q.x; v[j + 1] = q.y; v[j + 2] = q.z; v[j + 3] = q.w;
        tot += q.x + q.y + q.z + q.w;
    }

    int lane = tid & 31, wid = tid >> 5;
    int inc = tot;
    #pragma unroll
    for (int o = 1; o < 32; o <<= 1) {
        int y = __shfl_up_sync(0xffffffffu, inc, o);
        if (lane >= o) inc += y;
    }
    if (lane == 31) wsum[wid] = inc;
    __syncthreads();
    if (wid == 0) {
        int w = wsum[lane];
        #pragma unroll
        for (int o = 1; o < 32; o <<= 1) {
            int y = __shfl_up_sync(0xffffffffu, w, o);
            if (lane >= o) w += y;
        }
        wsum[lane] = w;
    }
    __syncthreads();

    int run = inc - tot + (wid ? wsum[wid - 1] : 0);
    #pragma unroll
    for (int j = 0; j < 32; j++) {
        g_off[base + j]  = run;
        g_fill[base + j] = run;
        run += v[j];
        g_cnt[base + j] = 0;          // reset histogram for next graph replay
    }
    if (tid == 1023) g_off[G3] = run;
}

// K3: scatter sources into cell-sorted order (order within a cell is
// nondeterministic, but min over a set is order-invariant -> deterministic output).
__global__ void scatter_kernel(const float* __restrict__ src) {
    int i = blockIdx.x * blockDim.x + threadIdx.x;
    if (i < NSRC) {
        int cid = g_scell[i];
        int pos = atomicAdd(&g_fill[cid], 1);
        g_s4[pos] = make_float4(src[3 * i + 0], src[3 * i + 1], src[3 * i + 2], 0.f);
    }
}

// K4: exact 1-NN via expanding Chebyshev shells with distance-bound early exit.
__global__ __launch_bounds__(SBLK) void search_kernel(const float* __restrict__ tar) {
    int i = blockIdx.x * SBLK + threadIdx.x;
    float best = 0.f;

    if (i < NTAR) {
        float tx = tar[3 * i + 0];
        float ty = tar[3 * i + 1];
        float tz = tar[3 * i + 2];
        int cx = cellc(tx), cy = cellc(ty), cz = cellc(tz);

        best = FLT_BIG;
        for (int r = 0; r < G; r++) {
            for (int dz = -r; dz <= r; dz++) {
                int z = cz + dz;
                if ((unsigned)z >= G) continue;
                bool zface = (dz == -r) || (dz == r);
                for (int dy = -r; dy <= r; dy++) {
                    int y = cy + dy;
                    if ((unsigned)y >= G) continue;
                    bool face = zface || (dy == -r) || (dy == r);
                    int rowbase = (z * G + y) * G;
                    int x0 = face ? (cx - r) : (cx - r);       // face rows: full span
                    int x1 = face ? (cx + r) : (cx + r);
                    if (face) {
                        int xa = max(cx - r, 0), xb = min(cx + r, G - 1);
                        int s = g_off[rowbase + xa];
                        int e = g_off[rowbase + xb + 1];        // contiguous x-run
                        for (int p = s; p < e; p++) {
                            float4 q = g_s4[p];
                            float dx = q.x - tx, dyv = q.y - ty, dzv = q.z - tz;
                            float d2 = fmaf(dx, dx, fmaf(dyv, dyv, dzv * dzv));
                            best = fminf(best, d2);
                        }
                    } else {
                        int x = cx - r;
                        if (x >= 0) {
                            int cid = rowbase + x;
                            int s = g_off[cid], e = g_off[cid + 1];
                            for (int p = s; p < e; p++) {
                                float4 q = g_s4[p];
                                float dx = q.x - tx, dyv = q.y - ty, dzv = q.z - tz;
                                float d2 = fmaf(dx, dx, fmaf(dyv, dyv, dzv * dzv));
                                best = fminf(best, d2);
                            }
                        }
                        x = cx + r;
                        if (x < G) {
                            int cid = rowbase + x;
                            int s = g_off[cid], e = g_off[cid + 1];
                            for (int p = s; p < e; p++) {
                                float4 q = g_s4[p];
                                float dx = q.x - tx, dyv = q.y - ty, dzv = q.z - tz;
                                float d2 = fmaf(dx, dx, fmaf(dyv, dyv, dzv * dzv));
                                best = fminf(best, d2);
                            }
                        }
                    }
                    (void)x0; (void)x1;
                }
            }
            float bnd = (float)r * H;
            if (best <= bnd * bnd) break;     // unscanned cells are >= r*H away
        }
    }

    // Block sum of per-target min d^2.
    __shared__ float ws[SBLK / 32];
    float s = best;
    for (int off = 16; off; off >>= 1)
        s += __shfl_down_sync(0xffffffffu, s, off);
    if ((threadIdx.x & 31) == 0) ws[threadIdx.x >> 5] = s;
    __syncthreads();
    if (threadIdx.x < 32) {
        float v = (threadIdx.x < SBLK / 32) ? ws[threadIdx.x] : 0.f;
        for (int off = 2; off; off >>= 1)
            v += __shfl_down_sync(0xffffffffu, v, off);
        if (threadIdx.x == 0) g_gsum[blockIdx.x] = v;
    }
}

// K5: deterministic final reduction.
__global__ void final_kernel(float* __restrict__ out) {
    float v = (threadIdx.x < NSB) ? g_gsum[threadIdx.x] : 0.f;
    for (int off = 16; off; off >>= 1)
        v += __shfl_down_sync(0xffffffffu, v, off);
    __shared__ float ws[8];
    if ((threadIdx.x & 31) == 0) ws[threadIdx.x >> 5] = v;
    __syncthreads();
    if (threadIdx.x == 0) {
        float s = 0.f;
        #pragma unroll
        for (int w = 0; w < 8; w++) s += ws[w];
        out[0] = 0.5f * s;
    }
}

extern "C" void kernel_launch(void* const* d_in, const int* in_sizes, int n_in,
                              void* d_out, int out_size) {
    const float* src = (const float*)d_in[0];   // [20000, 3] fp32
    const float* tar = (const float*)d_in[1];   // [20000, 3] fp32
    float* out = (float*)d_out;                 // scalar fp32

    count_kernel<<<(NSRC + 255) / 256, 256>>>(src);
    scan_kernel<<<1, 1024>>>();
    scatter_kernel<<<(NSRC + 255) / 256, 256>>>(src);
    search_kernel<<<NSB, SBLK>>>(tar);
    final_kernel<<<1, 256>>>(out);
}